// round 12
// baseline (speedup 1.0000x reference)
#include <cuda_runtime.h>
#include <math.h>

// ---------------- problem constants ----------------
#define Pn      50
#define NNODES  3200
#define EPGn    2048
#define En      131072
#define Bn      64
#define NPGn    50
#define D_LIN   1024
#define D_CONV  12544
#define D_REL   256
#define Kk      10
#define Xx      100

// node GEMM split-K: total K = 1024 + 12544 = 13568 = 53 * 256
#define NSEG    53
#define KSEG    256
#define BK      32
#define BM      128
#define PW      56      // padded P (50 -> 56) so both 28-col halves are 16B aligned
#define APITCH  33      // A smem pitch in float2 (duplicated pairs), conflict-free
#define NBLK_NODE (NSEG * (NNODES / BM))   // 53 * 25 = 1325
#define NBLK_REL  (En / BM)                // 1024

// ---------------- device scratch (static, no allocation) ----------------
__device__ float g_part[(size_t)NSEG * NNODES * Pn];   // split-K partials
__device__ float g_node[NNODES * Pn];                  // node features [3200,50]
__device__ float g_relT[(size_t)Pn * En];              // rel GEMM output, transposed [50, E]
__device__ float g_logits[Bn * Pn];
__device__ int   g_amax[Bn * Pn];
__device__ unsigned char g_srcl[En];
__device__ unsigned char g_dstl[En];
__device__ int   g_src[En];
__device__ int   g_dst[En];
__device__ float g_L1W[Pn];
__device__ float g_L1R[Pn];
__device__ int   g_is64;

// packed f32x2 FMA (SASS FFMA2): d.lo += a.lo*b.lo; d.hi += a.hi*b.hi
#define FMA2(d, a, b) \
    asm("fma.rn.f32x2 %0, %1, %2, %0;" : "+l"(d) : "l"(a), "l"(b))

// ---------------- dtype detection for relation_indexes ----------------
__global__ void detect_k(const int* __restrict__ ri) {
    int nz = 0;
    for (int i = 0; i < 64; i++) nz |= ri[2 * i + 1];
    g_is64 = (nz == 0) ? 1 : 0;
}

__global__ void prep_k(const int* __restrict__ ri) {
    int e = blockIdx.x * blockDim.x + threadIdx.x;
    if (e >= En) return;
    int s, d;
    if (g_is64) {
        s = (int)((const long long*)ri)[e];
        d = (int)((const long long*)ri)[En + e];
    } else {
        s = ri[e];
        d = ri[En + e];
    }
    g_src[e] = s;
    g_dst[e] = d;
    int b = e >> 11;
    g_srcl[e] = (unsigned char)(s - b * NPGn);
    g_dstl[e] = (unsigned char)(d - b * NPGn);
}

// ---------------- column L1 norms of the weight matrices ----------------
__global__ void l1_k(const float* __restrict__ Wo, const float* __restrict__ Wc,
                     const float* __restrict__ Wr) {
    int c = blockIdx.x;
    int t = threadIdx.x;  // 256 threads
    float sw = 0.f, sr = 0.f;
    for (int dd = t; dd < D_LIN; dd += 256)  sw += fabsf(Wo[dd * Pn + c]);
    for (int dd = t; dd < D_CONV; dd += 256) sw += fabsf(Wc[dd * Pn + c]);
    if (t < D_REL) sr = fabsf(Wr[t * Pn + c]);
    __shared__ float shw[256];
    __shared__ float shr[256];
    shw[t] = sw; shr[t] = sr;
    __syncthreads();
    for (int o = 128; o > 0; o >>= 1) {
        if (t < o) { shw[t] += shw[t + o]; shr[t] += shr[t + o]; }
        __syncthreads();
    }
    if (t == 0) { g_L1W[c] = shw[0]; g_L1R[c] = shr[0]; }
}

// ================= merged GEMM kernel =================
// 256 threads = 128 row-threads x 2 col-halves (28 padded cols each).
// Each thread: 1 row, 28 cols = 14 f32x2 accumulators.
// A tile stored duplicated in smem as (a,a) float2 (pitch 33 -> a-loads hit the
// 2-phase minimum for 256B, no extra conflicts). W loads are 16B warp broadcasts.
// Per kk per thread: 1 LDS.64 + 2 LDS.128 + 14 FFMA2 -> fma-pipe-bound mix.
__device__ __forceinline__ void gemm_tiles(
    const float* __restrict__ A, int lda,
    const float* __restrict__ W,   // [K, 50] row-major, tile rows contiguous
    int row0, int t,
    float2* Ad, float* Wsm, unsigned long long* acc) {

    int r  = t & 127;
    int c0 = (t >> 7) * 28;

    unsigned adbase = (unsigned)__cvta_generic_to_shared(Ad);
    unsigned abase  = adbase + (unsigned)(r * (APITCH * 8));
    unsigned wbase  = (unsigned)__cvta_generic_to_shared(Wsm) + (unsigned)(c0 * 4);

#pragma unroll
    for (int i = 0; i < 14; i++) acc[i] = 0ULL;

    // zero the pad columns (50..55) once; stays zero across tiles
    if (t < BK * 6) Wsm[(t / 6) * PW + 50 + (t % 6)] = 0.f;

    for (int tile = 0; tile < 8; tile++) {
        int kb = tile * BK;
        // ---- A tile: 128 rows x 32 k, float4 global loads, duplicated smem store
#pragma unroll
        for (int j = 0; j < 4; j++) {
            int idx = t + 256 * j;
            int rr = idx >> 3, q = idx & 7;
            float4 v = *reinterpret_cast<const float4*>(&A[(size_t)(row0 + rr) * lda + kb + q * 4]);
            float2* dst = &Ad[rr * APITCH + q * 4];
            dst[0] = make_float2(v.x, v.x);
            dst[1] = make_float2(v.y, v.y);
            dst[2] = make_float2(v.z, v.z);
            dst[3] = make_float2(v.w, v.w);
        }
        // ---- W tile: 32x50 contiguous span in global -> padded [32][56]
        {
            const float* Wt = W + (size_t)kb * Pn;
#pragma unroll
            for (int j2 = t; j2 < (BK * Pn) / 2; j2 += 256) {
                int j = j2 * 2;
                int kk = j / Pn;
                int c = j - kk * Pn;
                *reinterpret_cast<float2*>(&Wsm[kk * PW + c]) =
                    *reinterpret_cast<const float2*>(&Wt[j]);
            }
        }
        __syncthreads();

#pragma unroll 8
        for (int kk = 0; kk < BK; kk++) {
            unsigned long long a;
            asm("ld.shared.b64 %0, [%1];" : "=l"(a) : "r"(abase + kk * 8));
#pragma unroll
            for (int cq = 0; cq < 7; cq++) {
                unsigned long long w0, w1;
                asm("ld.shared.v2.u64 {%0, %1}, [%2];"
                    : "=l"(w0), "=l"(w1)
                    : "r"(wbase + kk * (PW * 4) + cq * 16));
                FMA2(acc[2 * cq],     a, w0);
                FMA2(acc[2 * cq + 1], a, w1);
            }
        }
        __syncthreads();
    }
}

__device__ __forceinline__ void unpack2(unsigned long long v, float& lo, float& hi) {
    asm("mov.b64 {%0, %1}, %2;" : "=f"(lo), "=f"(hi) : "l"(v));
}

// Blocks [0, 1325): node GEMM split-K segs (seg s: K range [s*256,(s+1)*256),
// segs 0..3 -> obj_lin, 4..52 -> obj_conv). Blocks [1325, 2349): rel GEMM.
__global__ void __launch_bounds__(256, 4) gemm_k(
    const float* __restrict__ obj_lin, const float* __restrict__ obj_conv,
    const float* __restrict__ rel_lin,
    const float* __restrict__ Wo, const float* __restrict__ Wc,
    const float* __restrict__ Wr) {
    __shared__ float2 Ad[BM * APITCH];
    __shared__ float  Wsm[BK * PW];
    int t = threadIdx.x;
    int blk = blockIdx.x;

    const float* A;
    const float* W;
    int lda, row0, s = 0;
    bool isrel = (blk >= NBLK_NODE);
    if (isrel) {
        row0 = (blk - NBLK_NODE) * BM;
        A = rel_lin; lda = D_REL; W = Wr;
    } else {
        int rb = blk % 25;
        s = blk / 25;
        row0 = rb * BM;
        if (s < 4) { A = obj_lin + (size_t)s * KSEG; lda = D_LIN; W = Wo + (size_t)s * KSEG * Pn; }
        else       { A = obj_conv + (size_t)(s * KSEG - D_LIN); lda = D_CONV; W = Wc + (size_t)(s * KSEG - D_LIN) * Pn; }
    }

    unsigned long long acc[14];
    gemm_tiles(A, lda, W, row0, t, Ad, Wsm, acc);

    int r = t & 127;
    int c0 = (t >> 7) * 28;
    if (!isrel) {
        float* o = g_part + ((size_t)s * NNODES + row0 + r) * Pn;
#pragma unroll
        for (int cq = 0; cq < 14; cq++) {
            int c = c0 + 2 * cq;
            if (c < Pn) {
                float lo, hi;
                unpack2(acc[cq], lo, hi);
                *reinterpret_cast<float2*>(&o[c]) = make_float2(lo, hi);
            }
        }
    } else {
        int e0 = row0 + r;
#pragma unroll
        for (int cq = 0; cq < 14; cq++) {
            int c = c0 + 2 * cq;
            if (c < Pn) {
                float lo, hi;
                unpack2(acc[cq], lo, hi);
                g_relT[(size_t)c * En + e0] = lo;
                g_relT[(size_t)(c + 1) * En + e0] = hi;
            }
        }
    }
}

// ---------------- split-K reduction (float4 streaming) ----------------
__global__ void node_reduce_k() {
    int i4 = blockIdx.x * 256 + threadIdx.x;
    if (i4 >= NNODES * Pn / 4) return;
    float4 s = make_float4(0.f, 0.f, 0.f, 0.f);
    const float4* p = reinterpret_cast<const float4*>(g_part) + i4;
#pragma unroll 4
    for (int seg = 0; seg < NSEG; seg++) {
        float4 v = p[(size_t)seg * (NNODES * Pn / 4)];
        s.x += v.x; s.y += v.y; s.z += v.z; s.w += v.w;
    }
    reinterpret_cast<float4*>(g_node)[i4] = s;
}

// ---------------- per (graph, class) max over 2048 edges, with argmax ----------------
__global__ void edge_max_k() {
    int bc = blockIdx.x;
    int b = bc / Pn, c = bc % Pn;
    __shared__ float nodesm[NPGn];
    int t = threadIdx.x;  // 256
    if (t < NPGn) nodesm[t] = g_node[(b * NPGn + t) * Pn + c];
    __syncthreads();
    const float* rptr = g_relT + (size_t)c * En + (size_t)b * EPGn;
    const unsigned char* sp = g_srcl + (size_t)b * EPGn;
    const unsigned char* dp = g_dstl + (size_t)b * EPGn;
    float best = -3.402823466e38f;
    int bi = 0;
    for (int e = t; e < EPGn; e += 256) {
        float v = rptr[e] + nodesm[sp[e]] + nodesm[dp[e]];
        if (v > best) { best = v; bi = e; }  // strict > keeps lowest index on ties
    }
    __shared__ float sv[256];
    __shared__ int si[256];
    sv[t] = best; si[t] = bi;
    __syncthreads();
    for (int o = 128; o > 0; o >>= 1) {
        if (t < o) {
            float v2 = sv[t + o];
            int i2 = si[t + o];
            if (v2 > sv[t] || (v2 == sv[t] && i2 < si[t])) { sv[t] = v2; si[t] = i2; }
        }
        __syncthreads();
    }
    if (t == 0) { g_logits[bc] = sv[0]; g_amax[bc] = si[0]; }
}

// ---------------- final: top-K classes, analytic relevances, top-X, outputs ----------------
__global__ void final_k(float* __restrict__ out) {
    int b = blockIdx.x;
    __shared__ float s_p[Kk];
    __shared__ int s_cls[Kk];
    __shared__ float s_val[Kk];
    __shared__ int s_fi[Kk];
    __shared__ int s_m;

    if (threadIdx.x == 0) {
        float pr[Pn];
        bool used[Pn];
        for (int c = 0; c < Pn; c++) {
            float x = g_logits[b * Pn + c];
            pr[c] = 1.f / (1.f + expf(-x));
            used[c] = false;
        }
        for (int k = 0; k < Kk; k++) {
            int bcx = 0;
            float bv = -1.f;
            for (int c = 0; c < Pn; c++)
                if (!used[c] && pr[c] > bv) { bv = pr[c]; bcx = c; }
            used[bcx] = true;
            s_cls[k] = bcx;
            s_p[k] = bv;
        }
        float tv[Kk];
        int tf[Kk];
        for (int k = 0; k < Kk; k++) {
            int c = s_cls[k];
            float x = g_logits[b * Pn + c];
            float p = s_p[k];
            float q = 1.f / (1.f + expf(x));
            float sg = p * q;
            int eloc = g_amax[b * Pn + c];
            int eg = b * EPGn + eloc;
            float mult = (g_srcl[eg] == g_dstl[eg]) ? 2.f : 1.f;
            float rn = mult * sg * g_L1W[c];
            float re = sg * g_L1R[c];
            tv[k] = rn * re * rn * p;
            tf[k] = eloc * Kk + k;
        }
        for (int i = 1; i < Kk; i++) {
            float v = tv[i];
            int f = tf[i];
            int j = i - 1;
            while (j >= 0 && (tv[j] < v || (tv[j] == v && tf[j] > f))) {
                tv[j + 1] = tv[j]; tf[j + 1] = tf[j]; j--;
            }
            tv[j + 1] = v; tf[j + 1] = f;
        }
        int m = 0;
        while (m < Kk && tv[m] > 0.f) m++;
        for (int k = 0; k < Kk; k++) { s_val[k] = tv[k]; s_fi[k] = tf[k]; }
        s_m = m;
    }
    __syncthreads();

    int m = s_m;
    for (int r = threadIdx.x; r < Xx; r += blockDim.x) {
        float val;
        int fi;
        if (r < m) {
            val = s_val[r];
            fi = s_fi[r];
        } else {
            int z = r - m;
            int x = z;
            for (int it = 0; it < Kk + 2; it++) {
                int cnt = 0;
                for (int i = 0; i < m; i++) cnt += (s_fi[i] <= x) ? 1 : 0;
                int nx = z + cnt;
                if (nx == x) break;
                x = nx;
            }
            val = 0.f;
            fi = x;
        }
        int k = fi % Kk;
        int eloc = fi / Kk;
        int eg = b * EPGn + eloc;
        int o = b * Xx + r;
        out[o]          = val;
        out[6400 + o]   = (float)g_src[eg];
        out[12800 + o]  = (float)g_dst[eg];
        out[19200 + o]  = s_p[k];
        out[25600 + o]  = (float)s_cls[k];
    }
    if (threadIdx.x == 0) out[32000 + b] = 100.f;
}

// ---------------- launcher ----------------
extern "C" void kernel_launch(void* const* d_in, const int* in_sizes, int n_in,
                              void* d_out, int out_size) {
    const float* obj_lin  = (const float*)d_in[0];
    const float* obj_conv = (const float*)d_in[1];
    const float* rel_lin  = (const float*)d_in[2];
    const int*   ri       = (const int*)d_in[3];
    const float* W_obj    = (const float*)d_in[4];
    const float* W_conv   = (const float*)d_in[5];
    const float* W_rel    = (const float*)d_in[6];
    float* out = (float*)d_out;

    detect_k<<<1, 1>>>(ri);
    prep_k<<<(En + 255) / 256, 256>>>(ri);
    l1_k<<<Pn, 256>>>(W_obj, W_conv, W_rel);
    gemm_k<<<NBLK_NODE + NBLK_REL, 256>>>(obj_lin, obj_conv, rel_lin, W_obj, W_conv, W_rel);
    node_reduce_k<<<(NNODES * Pn / 4 + 255) / 256, 256>>>();
    edge_max_k<<<Bn * Pn, 256>>>();
    final_k<<<Bn, 32>>>(out);
}

// round 13
// speedup vs baseline: 1.2538x; 1.2538x over previous
#include <cuda_runtime.h>
#include <math.h>

// ---------------- problem constants ----------------
#define Pn      50
#define NNODES  3200
#define EPGn    2048
#define En      131072
#define Bn      64
#define NPGn    50
#define D_LIN   1024
#define D_CONV  12544
#define D_REL   256
#define Kk      10
#define Xx      100

// node GEMM split-K: total K = 1024 + 12544 = 13568 = 53 * 256
#define NSEG    53
#define KSEG    256
#define BK      32
#define BM      128
#define PW      56      // padded P (50 -> 56) so both 28-col halves are 16B aligned
#define APITCH  33      // A smem pitch in floats: conflict-free loads AND stores
#define NBLK_NODE (NSEG * (NNODES / BM))   // 53 * 25 = 1325
#define NBLK_REL  (En / BM)                // 1024

// ---------------- device scratch (static, no allocation) ----------------
__device__ float g_part[(size_t)NSEG * NNODES * Pn];   // split-K partials
__device__ float g_node[NNODES * Pn];                  // node features [3200,50]
__device__ float g_relT[(size_t)Pn * En];              // rel GEMM output, transposed [50, E]
__device__ float g_logits[Bn * Pn];
__device__ int   g_amax[Bn * Pn];
__device__ unsigned char g_srcl[En];
__device__ unsigned char g_dstl[En];
__device__ int   g_src[En];
__device__ int   g_dst[En];
__device__ float g_L1W[Pn];
__device__ float g_L1R[Pn];
__device__ int   g_is64;

// packed f32x2 FMA (SASS FFMA2): d.lo += a.lo*b.lo; d.hi += a.hi*b.hi
#define FMA2(d, a, b) \
    asm("fma.rn.f32x2 %0, %1, %2, %0;" : "+l"(d) : "l"(a), "l"(b))

// ---------------- dtype detection for relation_indexes ----------------
__global__ void detect_k(const int* __restrict__ ri) {
    int nz = 0;
    for (int i = 0; i < 64; i++) nz |= ri[2 * i + 1];
    g_is64 = (nz == 0) ? 1 : 0;
}

__global__ void prep_k(const int* __restrict__ ri) {
    int e = blockIdx.x * blockDim.x + threadIdx.x;
    if (e >= En) return;
    int s, d;
    if (g_is64) {
        s = (int)((const long long*)ri)[e];
        d = (int)((const long long*)ri)[En + e];
    } else {
        s = ri[e];
        d = ri[En + e];
    }
    g_src[e] = s;
    g_dst[e] = d;
    int b = e >> 11;
    g_srcl[e] = (unsigned char)(s - b * NPGn);
    g_dstl[e] = (unsigned char)(d - b * NPGn);
}

// ---------------- column L1 norms of the weight matrices ----------------
__global__ void l1_k(const float* __restrict__ Wo, const float* __restrict__ Wc,
                     const float* __restrict__ Wr) {
    int c = blockIdx.x;
    int t = threadIdx.x;  // 256 threads
    float sw = 0.f, sr = 0.f;
    for (int dd = t; dd < D_LIN; dd += 256)  sw += fabsf(Wo[dd * Pn + c]);
    for (int dd = t; dd < D_CONV; dd += 256) sw += fabsf(Wc[dd * Pn + c]);
    if (t < D_REL) sr = fabsf(Wr[t * Pn + c]);
    __shared__ float shw[256];
    __shared__ float shr[256];
    shw[t] = sw; shr[t] = sr;
    __syncthreads();
    for (int o = 128; o > 0; o >>= 1) {
        if (t < o) { shw[t] += shw[t + o]; shr[t] += shr[t + o]; }
        __syncthreads();
    }
    if (t == 0) { g_L1W[c] = shw[0]; g_L1R[c] = shr[0]; }
}

// ================= merged GEMM kernel =================
// 64 threads = 32 row-threads x 2 col-halves (28 padded cols each).
// Each thread: 4 rows (lane, lane+32, lane+64, lane+96) x 28 cols
// -> 4x14 f32x2 accumulators (112 regs).
// Per kk per thread: 4 LDS.32 (a) + 4 mov.b64 (pack) + 7 LDS.128 (w broadcast)
// + 56 FFMA2. fma-pipe demand 112 cyc/warp/kk vs crossbar ~11 phases -> fma-bound.
__device__ __forceinline__ void gemm_tiles(
    const float* __restrict__ A, int lda,
    const float* __restrict__ W,   // [K, 50] row-major, tile rows contiguous
    int row0, int t,
    float* Asm, float* Wsm, unsigned long long acc[4][14]) {

    int lane = t & 31;
    int c0 = (t >> 5) * 28;   // warp-uniform -> W loads are broadcasts

    unsigned abase = (unsigned)__cvta_generic_to_shared(Asm) + (unsigned)(lane * (APITCH * 4));
    unsigned wbase = (unsigned)__cvta_generic_to_shared(Wsm) + (unsigned)(c0 * 4);

#pragma unroll
    for (int m = 0; m < 4; m++)
#pragma unroll
        for (int i = 0; i < 14; i++) acc[m][i] = 0ULL;

    // zero the pad columns (50..55) once; stays zero across tiles
    for (int j = t; j < BK * 6; j += 64) Wsm[(j / 6) * PW + 50 + (j % 6)] = 0.f;

    for (int tile = 0; tile < 8; tile++) {
        int kb = tile * BK;
        // ---- A tile: 128 rows x 32 k. float4 global loads, 4 scalar smem stores
        // (pitch 33 floats: both stores and inner-loop loads are conflict-free).
#pragma unroll
        for (int j = 0; j < 16; j++) {
            int idx = t + 64 * j;
            int rr = idx >> 3, q = idx & 7;
            float4 v = *reinterpret_cast<const float4*>(&A[(size_t)(row0 + rr) * lda + kb + q * 4]);
            float* dst = &Asm[rr * APITCH + q * 4];
            dst[0] = v.x; dst[1] = v.y; dst[2] = v.z; dst[3] = v.w;
        }
        // ---- W tile: 32x50 contiguous span in global -> padded [32][56]
        {
            const float* Wt = W + (size_t)kb * Pn;
#pragma unroll
            for (int j2 = t; j2 < (BK * Pn) / 2; j2 += 64) {
                int j = j2 * 2;
                int kk = j / Pn;
                int c = j - kk * Pn;
                *reinterpret_cast<float2*>(&Wsm[kk * PW + c]) =
                    *reinterpret_cast<const float2*>(&Wt[j]);
            }
        }
        __syncthreads();

#pragma unroll 4
        for (int kk = 0; kk < BK; kk++) {
            float a0, a1, a2, a3;
            asm("ld.shared.f32 %0, [%1];" : "=f"(a0) : "r"(abase + kk * 4));
            asm("ld.shared.f32 %0, [%1];" : "=f"(a1) : "r"(abase + kk * 4 + 32 * APITCH * 4));
            asm("ld.shared.f32 %0, [%1];" : "=f"(a2) : "r"(abase + kk * 4 + 64 * APITCH * 4));
            asm("ld.shared.f32 %0, [%1];" : "=f"(a3) : "r"(abase + kk * 4 + 96 * APITCH * 4));
            unsigned long long pa0, pa1, pa2, pa3;
            asm("mov.b64 %0, {%1, %1};" : "=l"(pa0) : "f"(a0));
            asm("mov.b64 %0, {%1, %1};" : "=l"(pa1) : "f"(a1));
            asm("mov.b64 %0, {%1, %1};" : "=l"(pa2) : "f"(a2));
            asm("mov.b64 %0, {%1, %1};" : "=l"(pa3) : "f"(a3));
#pragma unroll
            for (int cq = 0; cq < 7; cq++) {
                unsigned long long w0, w1;
                asm("ld.shared.v2.u64 {%0, %1}, [%2];"
                    : "=l"(w0), "=l"(w1)
                    : "r"(wbase + kk * (PW * 4) + cq * 16));
                FMA2(acc[0][2 * cq],     pa0, w0);
                FMA2(acc[0][2 * cq + 1], pa0, w1);
                FMA2(acc[1][2 * cq],     pa1, w0);
                FMA2(acc[1][2 * cq + 1], pa1, w1);
                FMA2(acc[2][2 * cq],     pa2, w0);
                FMA2(acc[2][2 * cq + 1], pa2, w1);
                FMA2(acc[3][2 * cq],     pa3, w0);
                FMA2(acc[3][2 * cq + 1], pa3, w1);
            }
        }
        __syncthreads();
    }
}

__device__ __forceinline__ void unpack2(unsigned long long v, float& lo, float& hi) {
    asm("mov.b64 {%0, %1}, %2;" : "=f"(lo), "=f"(hi) : "l"(v));
}

// Blocks [0, 1325): node GEMM split-K segs (seg s: K range [s*256,(s+1)*256),
// segs 0..3 -> obj_lin, 4..52 -> obj_conv). Blocks [1325, 2349): rel GEMM.
__global__ void __launch_bounds__(64, 6) gemm_k(
    const float* __restrict__ obj_lin, const float* __restrict__ obj_conv,
    const float* __restrict__ rel_lin,
    const float* __restrict__ Wo, const float* __restrict__ Wc,
    const float* __restrict__ Wr) {
    __shared__ float Asm[BM * APITCH];
    __shared__ float Wsm[BK * PW];
    int t = threadIdx.x;
    int blk = blockIdx.x;

    const float* A;
    const float* W;
    int lda, row0, s = 0;
    bool isrel = (blk >= NBLK_NODE);
    if (isrel) {
        row0 = (blk - NBLK_NODE) * BM;
        A = rel_lin; lda = D_REL; W = Wr;
    } else {
        int rb = blk % 25;
        s = blk / 25;
        row0 = rb * BM;
        if (s < 4) { A = obj_lin + (size_t)s * KSEG; lda = D_LIN; W = Wo + (size_t)s * KSEG * Pn; }
        else       { A = obj_conv + (size_t)(s * KSEG - D_LIN); lda = D_CONV; W = Wc + (size_t)(s * KSEG - D_LIN) * Pn; }
    }

    unsigned long long acc[4][14];
    gemm_tiles(A, lda, W, row0, t, Asm, Wsm, acc);

    int lane = t & 31;
    int c0 = (t >> 5) * 28;
    if (!isrel) {
#pragma unroll
        for (int m = 0; m < 4; m++) {
            int row = lane + 32 * m;
            float* o = g_part + ((size_t)s * NNODES + row0 + row) * Pn;
#pragma unroll
            for (int cq = 0; cq < 14; cq++) {
                int c = c0 + 2 * cq;
                if (c < Pn) {
                    float lo, hi;
                    unpack2(acc[m][cq], lo, hi);
                    *reinterpret_cast<float2*>(&o[c]) = make_float2(lo, hi);
                }
            }
        }
    } else {
#pragma unroll
        for (int m = 0; m < 4; m++) {
            int e0 = row0 + lane + 32 * m;
#pragma unroll
            for (int cq = 0; cq < 14; cq++) {
                int c = c0 + 2 * cq;
                if (c < Pn) {
                    float lo, hi;
                    unpack2(acc[m][cq], lo, hi);
                    g_relT[(size_t)c * En + e0] = lo;
                    g_relT[(size_t)(c + 1) * En + e0] = hi;
                }
            }
        }
    }
}

// ---------------- split-K reduction (float4 streaming) ----------------
__global__ void node_reduce_k() {
    int i4 = blockIdx.x * 256 + threadIdx.x;
    if (i4 >= NNODES * Pn / 4) return;
    float4 s = make_float4(0.f, 0.f, 0.f, 0.f);
    const float4* p = reinterpret_cast<const float4*>(g_part) + i4;
#pragma unroll 4
    for (int seg = 0; seg < NSEG; seg++) {
        float4 v = p[(size_t)seg * (NNODES * Pn / 4)];
        s.x += v.x; s.y += v.y; s.z += v.z; s.w += v.w;
    }
    reinterpret_cast<float4*>(g_node)[i4] = s;
}

// ---------------- per (graph, class) max over 2048 edges, with argmax ----------------
__global__ void edge_max_k() {
    int bc = blockIdx.x;
    int b = bc / Pn, c = bc % Pn;
    __shared__ float nodesm[NPGn];
    int t = threadIdx.x;  // 256
    if (t < NPGn) nodesm[t] = g_node[(b * NPGn + t) * Pn + c];
    __syncthreads();
    const float* rptr = g_relT + (size_t)c * En + (size_t)b * EPGn;
    const unsigned char* sp = g_srcl + (size_t)b * EPGn;
    const unsigned char* dp = g_dstl + (size_t)b * EPGn;
    float best = -3.402823466e38f;
    int bi = 0;
    for (int e = t; e < EPGn; e += 256) {
        float v = rptr[e] + nodesm[sp[e]] + nodesm[dp[e]];
        if (v > best) { best = v; bi = e; }  // strict > keeps lowest index on ties
    }
    __shared__ float sv[256];
    __shared__ int si[256];
    sv[t] = best; si[t] = bi;
    __syncthreads();
    for (int o = 128; o > 0; o >>= 1) {
        if (t < o) {
            float v2 = sv[t + o];
            int i2 = si[t + o];
            if (v2 > sv[t] || (v2 == sv[t] && i2 < si[t])) { sv[t] = v2; si[t] = i2; }
        }
        __syncthreads();
    }
    if (t == 0) { g_logits[bc] = sv[0]; g_amax[bc] = si[0]; }
}

// ---------------- final: top-K classes, analytic relevances, top-X, outputs ----------------
__global__ void final_k(float* __restrict__ out) {
    int b = blockIdx.x;
    __shared__ float s_p[Kk];
    __shared__ int s_cls[Kk];
    __shared__ float s_val[Kk];
    __shared__ int s_fi[Kk];
    __shared__ int s_m;

    if (threadIdx.x == 0) {
        float pr[Pn];
        bool used[Pn];
        for (int c = 0; c < Pn; c++) {
            float x = g_logits[b * Pn + c];
            pr[c] = 1.f / (1.f + expf(-x));
            used[c] = false;
        }
        for (int k = 0; k < Kk; k++) {
            int bcx = 0;
            float bv = -1.f;
            for (int c = 0; c < Pn; c++)
                if (!used[c] && pr[c] > bv) { bv = pr[c]; bcx = c; }
            used[bcx] = true;
            s_cls[k] = bcx;
            s_p[k] = bv;
        }
        float tv[Kk];
        int tf[Kk];
        for (int k = 0; k < Kk; k++) {
            int c = s_cls[k];
            float x = g_logits[b * Pn + c];
            float p = s_p[k];
            float q = 1.f / (1.f + expf(x));
            float sg = p * q;
            int eloc = g_amax[b * Pn + c];
            int eg = b * EPGn + eloc;
            float mult = (g_srcl[eg] == g_dstl[eg]) ? 2.f : 1.f;
            float rn = mult * sg * g_L1W[c];
            float re = sg * g_L1R[c];
            tv[k] = rn * re * rn * p;
            tf[k] = eloc * Kk + k;
        }
        for (int i = 1; i < Kk; i++) {
            float v = tv[i];
            int f = tf[i];
            int j = i - 1;
            while (j >= 0 && (tv[j] < v || (tv[j] == v && tf[j] > f))) {
                tv[j + 1] = tv[j]; tf[j + 1] = tf[j]; j--;
            }
            tv[j + 1] = v; tf[j + 1] = f;
        }
        int m = 0;
        while (m < Kk && tv[m] > 0.f) m++;
        for (int k = 0; k < Kk; k++) { s_val[k] = tv[k]; s_fi[k] = tf[k]; }
        s_m = m;
    }
    __syncthreads();

    int m = s_m;
    for (int r = threadIdx.x; r < Xx; r += blockDim.x) {
        float val;
        int fi;
        if (r < m) {
            val = s_val[r];
            fi = s_fi[r];
        } else {
            int z = r - m;
            int x = z;
            for (int it = 0; it < Kk + 2; it++) {
                int cnt = 0;
                for (int i = 0; i < m; i++) cnt += (s_fi[i] <= x) ? 1 : 0;
                int nx = z + cnt;
                if (nx == x) break;
                x = nx;
            }
            val = 0.f;
            fi = x;
        }
        int k = fi % Kk;
        int eloc = fi / Kk;
        int eg = b * EPGn + eloc;
        int o = b * Xx + r;
        out[o]          = val;
        out[6400 + o]   = (float)g_src[eg];
        out[12800 + o]  = (float)g_dst[eg];
        out[19200 + o]  = s_p[k];
        out[25600 + o]  = (float)s_cls[k];
    }
    if (threadIdx.x == 0) out[32000 + b] = 100.f;
}

// ---------------- launcher ----------------
extern "C" void kernel_launch(void* const* d_in, const int* in_sizes, int n_in,
                              void* d_out, int out_size) {
    const float* obj_lin  = (const float*)d_in[0];
    const float* obj_conv = (const float*)d_in[1];
    const float* rel_lin  = (const float*)d_in[2];
    const int*   ri       = (const int*)d_in[3];
    const float* W_obj    = (const float*)d_in[4];
    const float* W_conv   = (const float*)d_in[5];
    const float* W_rel    = (const float*)d_in[6];
    float* out = (float*)d_out;

    detect_k<<<1, 1>>>(ri);
    prep_k<<<(En + 255) / 256, 256>>>(ri);
    l1_k<<<Pn, 256>>>(W_obj, W_conv, W_rel);
    gemm_k<<<NBLK_NODE + NBLK_REL, 64>>>(obj_lin, obj_conv, rel_lin, W_obj, W_conv, W_rel);
    node_reduce_k<<<(NNODES * Pn / 4 + 255) / 256, 256>>>();
    edge_max_k<<<Bn * Pn, 256>>>();
    final_k<<<Bn, 32>>>(out);
}

// round 14
// speedup vs baseline: 1.3158x; 1.0494x over previous
#include <cuda_runtime.h>
#include <math.h>

// ---------------- problem constants ----------------
#define Pn      50
#define NNODES  3200
#define EPGn    2048
#define En      131072
#define Bn      64
#define NPGn    50
#define D_LIN   1024
#define D_CONV  12544
#define D_REL   256
#define Kk      10
#define Xx      100

// node GEMM split-K: total K = 1024 + 12544 = 13568 = 53 * 256
#define NSEG    53
#define KSEG    256
#define BK      32
#define BM      128
#define PW      56      // padded P (50 -> 56) so both 28-col halves are 16B aligned
#define APITCH  33      // A smem pitch in floats: conflict-free loads AND stores
#define NBLK_NODE (NSEG * (NNODES / BM))   // 53 * 25 = 1325
#define NBLK_REL  (En / BM)                // 1024

// ---------------- device scratch (static, no allocation) ----------------
__device__ float g_part[(size_t)NSEG * NNODES * Pn];   // split-K partials
__device__ float g_node[NNODES * Pn];                  // node features [3200,50]
__device__ float g_relT[(size_t)Pn * En];              // rel GEMM output, transposed [50, E]
__device__ float g_logits[Bn * Pn];
__device__ int   g_amax[Bn * Pn];
__device__ unsigned char g_srcl[En];
__device__ unsigned char g_dstl[En];
__device__ int   g_src[En];
__device__ int   g_dst[En];
__device__ float g_L1W[Pn];
__device__ float g_L1R[Pn];
__device__ int   g_is64;

// packed f32x2 FMA (SASS FFMA2): d.lo += a.lo*b.lo; d.hi += a.hi*b.hi
#define FMA2(d, a, b) \
    asm("fma.rn.f32x2 %0, %1, %2, %0;" : "+l"(d) : "l"(a), "l"(b))

// ---------------- dtype detection for relation_indexes ----------------
__global__ void detect_k(const int* __restrict__ ri) {
    int nz = 0;
    for (int i = 0; i < 64; i++) nz |= ri[2 * i + 1];
    g_is64 = (nz == 0) ? 1 : 0;
}

__global__ void prep_k(const int* __restrict__ ri) {
    int e = blockIdx.x * blockDim.x + threadIdx.x;
    if (e >= En) return;
    int s, d;
    if (g_is64) {
        s = (int)((const long long*)ri)[e];
        d = (int)((const long long*)ri)[En + e];
    } else {
        s = ri[e];
        d = ri[En + e];
    }
    g_src[e] = s;
    g_dst[e] = d;
    int b = e >> 11;
    g_srcl[e] = (unsigned char)(s - b * NPGn);
    g_dstl[e] = (unsigned char)(d - b * NPGn);
}

// ---------------- column L1 norms of the weight matrices ----------------
__global__ void l1_k(const float* __restrict__ Wo, const float* __restrict__ Wc,
                     const float* __restrict__ Wr) {
    int c = blockIdx.x;
    int t = threadIdx.x;  // 256 threads
    float sw = 0.f, sr = 0.f;
    for (int dd = t; dd < D_LIN; dd += 256)  sw += fabsf(Wo[dd * Pn + c]);
    for (int dd = t; dd < D_CONV; dd += 256) sw += fabsf(Wc[dd * Pn + c]);
    if (t < D_REL) sr = fabsf(Wr[t * Pn + c]);
    __shared__ float shw[256];
    __shared__ float shr[256];
    shw[t] = sw; shr[t] = sr;
    __syncthreads();
    for (int o = 128; o > 0; o >>= 1) {
        if (t < o) { shw[t] += shw[t + o]; shr[t] += shr[t + o]; }
        __syncthreads();
    }
    if (t == 0) { g_L1W[c] = shw[0]; g_L1R[c] = shr[0]; }
}

// ================= merged GEMM kernel =================
// 128 threads = 64 row-threads x 2 col-halves (28 padded cols each).
// Each thread: 2 rows (r, r+64) x 28 cols -> 2x14 f32x2 accumulators (56 regs).
// Per kk per warp: 2 LDS.32 (conflict-free) + 2 mov.b64 pack + 7 LDS.128
// (warp-broadcast) + 28 FFMA2 (56 fma-pipe cyc) -> fma-bound at >=3 warps/SMSP.
// launch_bounds(128,5): 5 blocks/SM = 20 warps = 5 warps/SMSP for latency hiding.
__device__ __forceinline__ void gemm_tiles(
    const float* __restrict__ A, int lda,
    const float* __restrict__ W,   // [K, 50] row-major, tile rows contiguous
    int row0, int t,
    float* Asm, float* Wsm, unsigned long long acc[2][14]) {

    int r  = t & 63;
    int c0 = (t >> 6) * 28;   // warp-uniform (warps 0,1 -> 0; warps 2,3 -> 28)

    unsigned abase = (unsigned)__cvta_generic_to_shared(Asm) + (unsigned)(r * (APITCH * 4));
    unsigned wbase = (unsigned)__cvta_generic_to_shared(Wsm) + (unsigned)(c0 * 4);

#pragma unroll
    for (int m = 0; m < 2; m++)
#pragma unroll
        for (int i = 0; i < 14; i++) acc[m][i] = 0ULL;

    // zero the pad columns (50..55) once; stays zero across tiles
    for (int j = t; j < BK * 6; j += 128) Wsm[(j / 6) * PW + 50 + (j % 6)] = 0.f;

    for (int tile = 0; tile < 8; tile++) {
        int kb = tile * BK;
        // ---- A tile: 128 rows x 32 k. float4 global loads, scalar smem stores
        // (pitch 33 floats: stores and inner-loop loads conflict-free).
#pragma unroll
        for (int j = 0; j < 8; j++) {
            int idx = t + 128 * j;
            int rr = idx >> 3, q = idx & 7;
            float4 v = *reinterpret_cast<const float4*>(&A[(size_t)(row0 + rr) * lda + kb + q * 4]);
            float* dst = &Asm[rr * APITCH + q * 4];
            dst[0] = v.x; dst[1] = v.y; dst[2] = v.z; dst[3] = v.w;
        }
        // ---- W tile: 32x50 contiguous span in global -> padded [32][56]
        {
            const float* Wt = W + (size_t)kb * Pn;
#pragma unroll
            for (int j2 = t; j2 < (BK * Pn) / 2; j2 += 128) {
                int j = j2 * 2;
                int kk = j / Pn;
                int c = j - kk * Pn;
                *reinterpret_cast<float2*>(&Wsm[kk * PW + c]) =
                    *reinterpret_cast<const float2*>(&Wt[j]);
            }
        }
        __syncthreads();

#pragma unroll 4
        for (int kk = 0; kk < BK; kk++) {
            float a0, a1;
            asm("ld.shared.f32 %0, [%1];" : "=f"(a0) : "r"(abase + kk * 4));
            asm("ld.shared.f32 %0, [%1];" : "=f"(a1) : "r"(abase + kk * 4 + 64 * APITCH * 4));
            unsigned long long pa0, pa1;
            asm("mov.b64 %0, {%1, %1};" : "=l"(pa0) : "f"(a0));
            asm("mov.b64 %0, {%1, %1};" : "=l"(pa1) : "f"(a1));
#pragma unroll
            for (int cq = 0; cq < 7; cq++) {
                unsigned long long w0, w1;
                asm("ld.shared.v2.u64 {%0, %1}, [%2];"
                    : "=l"(w0), "=l"(w1)
                    : "r"(wbase + kk * (PW * 4) + cq * 16));
                FMA2(acc[0][2 * cq],     pa0, w0);
                FMA2(acc[0][2 * cq + 1], pa0, w1);
                FMA2(acc[1][2 * cq],     pa1, w0);
                FMA2(acc[1][2 * cq + 1], pa1, w1);
            }
        }
        __syncthreads();
    }
}

__device__ __forceinline__ void unpack2(unsigned long long v, float& lo, float& hi) {
    asm("mov.b64 {%0, %1}, %2;" : "=f"(lo), "=f"(hi) : "l"(v));
}

// Blocks [0, 1325): node GEMM split-K segs (seg s: K range [s*256,(s+1)*256),
// segs 0..3 -> obj_lin, 4..52 -> obj_conv). Blocks [1325, 2349): rel GEMM.
__global__ void __launch_bounds__(128, 5) gemm_k(
    const float* __restrict__ obj_lin, const float* __restrict__ obj_conv,
    const float* __restrict__ rel_lin,
    const float* __restrict__ Wo, const float* __restrict__ Wc,
    const float* __restrict__ Wr) {
    __shared__ float Asm[BM * APITCH];
    __shared__ float Wsm[BK * PW];
    int t = threadIdx.x;
    int blk = blockIdx.x;

    const float* A;
    const float* W;
    int lda, row0, s = 0;
    bool isrel = (blk >= NBLK_NODE);
    if (isrel) {
        row0 = (blk - NBLK_NODE) * BM;
        A = rel_lin; lda = D_REL; W = Wr;
    } else {
        int rb = blk % 25;
        s = blk / 25;
        row0 = rb * BM;
        if (s < 4) { A = obj_lin + (size_t)s * KSEG; lda = D_LIN; W = Wo + (size_t)s * KSEG * Pn; }
        else       { A = obj_conv + (size_t)(s * KSEG - D_LIN); lda = D_CONV; W = Wc + (size_t)(s * KSEG - D_LIN) * Pn; }
    }

    unsigned long long acc[2][14];
    gemm_tiles(A, lda, W, row0, t, Asm, Wsm, acc);

    int r = t & 63;
    int c0 = (t >> 6) * 28;
    if (!isrel) {
#pragma unroll
        for (int m = 0; m < 2; m++) {
            int row = r + 64 * m;
            float* o = g_part + ((size_t)s * NNODES + row0 + row) * Pn;
#pragma unroll
            for (int cq = 0; cq < 14; cq++) {
                int c = c0 + 2 * cq;
                if (c < Pn) {
                    float lo, hi;
                    unpack2(acc[m][cq], lo, hi);
                    *reinterpret_cast<float2*>(&o[c]) = make_float2(lo, hi);
                }
            }
        }
    } else {
#pragma unroll
        for (int m = 0; m < 2; m++) {
            int e0 = row0 + r + 64 * m;
#pragma unroll
            for (int cq = 0; cq < 14; cq++) {
                int c = c0 + 2 * cq;
                if (c < Pn) {
                    float lo, hi;
                    unpack2(acc[m][cq], lo, hi);
                    g_relT[(size_t)c * En + e0] = lo;
                    g_relT[(size_t)(c + 1) * En + e0] = hi;
                }
            }
        }
    }
}

// ---------------- split-K reduction (float4 streaming) ----------------
__global__ void node_reduce_k() {
    int i4 = blockIdx.x * 256 + threadIdx.x;
    if (i4 >= NNODES * Pn / 4) return;
    float4 s = make_float4(0.f, 0.f, 0.f, 0.f);
    const float4* p = reinterpret_cast<const float4*>(g_part) + i4;
#pragma unroll 4
    for (int seg = 0; seg < NSEG; seg++) {
        float4 v = p[(size_t)seg * (NNODES * Pn / 4)];
        s.x += v.x; s.y += v.y; s.z += v.z; s.w += v.w;
    }
    reinterpret_cast<float4*>(g_node)[i4] = s;
}

// ---------------- per (graph, class) max over 2048 edges, with argmax ----------------
__global__ void edge_max_k() {
    int bc = blockIdx.x;
    int b = bc / Pn, c = bc % Pn;
    __shared__ float nodesm[NPGn];
    int t = threadIdx.x;  // 256
    if (t < NPGn) nodesm[t] = g_node[(b * NPGn + t) * Pn + c];
    __syncthreads();
    const float* rptr = g_relT + (size_t)c * En + (size_t)b * EPGn;
    const unsigned char* sp = g_srcl + (size_t)b * EPGn;
    const unsigned char* dp = g_dstl + (size_t)b * EPGn;
    float best = -3.402823466e38f;
    int bi = 0;
    for (int e = t; e < EPGn; e += 256) {
        float v = rptr[e] + nodesm[sp[e]] + nodesm[dp[e]];
        if (v > best) { best = v; bi = e; }  // strict > keeps lowest index on ties
    }
    __shared__ float sv[256];
    __shared__ int si[256];
    sv[t] = best; si[t] = bi;
    __syncthreads();
    for (int o = 128; o > 0; o >>= 1) {
        if (t < o) {
            float v2 = sv[t + o];
            int i2 = si[t + o];
            if (v2 > sv[t] || (v2 == sv[t] && i2 < si[t])) { sv[t] = v2; si[t] = i2; }
        }
        __syncthreads();
    }
    if (t == 0) { g_logits[bc] = sv[0]; g_amax[bc] = si[0]; }
}

// ---------------- final: top-K classes, analytic relevances, top-X, outputs ----------------
__global__ void final_k(float* __restrict__ out) {
    int b = blockIdx.x;
    __shared__ float s_p[Kk];
    __shared__ int s_cls[Kk];
    __shared__ float s_val[Kk];
    __shared__ int s_fi[Kk];
    __shared__ int s_m;

    if (threadIdx.x == 0) {
        float pr[Pn];
        bool used[Pn];
        for (int c = 0; c < Pn; c++) {
            float x = g_logits[b * Pn + c];
            pr[c] = 1.f / (1.f + expf(-x));
            used[c] = false;
        }
        for (int k = 0; k < Kk; k++) {
            int bcx = 0;
            float bv = -1.f;
            for (int c = 0; c < Pn; c++)
                if (!used[c] && pr[c] > bv) { bv = pr[c]; bcx = c; }
            used[bcx] = true;
            s_cls[k] = bcx;
            s_p[k] = bv;
        }
        float tv[Kk];
        int tf[Kk];
        for (int k = 0; k < Kk; k++) {
            int c = s_cls[k];
            float x = g_logits[b * Pn + c];
            float p = s_p[k];
            float q = 1.f / (1.f + expf(x));
            float sg = p * q;
            int eloc = g_amax[b * Pn + c];
            int eg = b * EPGn + eloc;
            float mult = (g_srcl[eg] == g_dstl[eg]) ? 2.f : 1.f;
            float rn = mult * sg * g_L1W[c];
            float re = sg * g_L1R[c];
            tv[k] = rn * re * rn * p;
            tf[k] = eloc * Kk + k;
        }
        for (int i = 1; i < Kk; i++) {
            float v = tv[i];
            int f = tf[i];
            int j = i - 1;
            while (j >= 0 && (tv[j] < v || (tv[j] == v && tf[j] > f))) {
                tv[j + 1] = tv[j]; tf[j + 1] = tf[j]; j--;
            }
            tv[j + 1] = v; tf[j + 1] = f;
        }
        int m = 0;
        while (m < Kk && tv[m] > 0.f) m++;
        for (int k = 0; k < Kk; k++) { s_val[k] = tv[k]; s_fi[k] = tf[k]; }
        s_m = m;
    }
    __syncthreads();

    int m = s_m;
    for (int r = threadIdx.x; r < Xx; r += blockDim.x) {
        float val;
        int fi;
        if (r < m) {
            val = s_val[r];
            fi = s_fi[r];
        } else {
            int z = r - m;
            int x = z;
            for (int it = 0; it < Kk + 2; it++) {
                int cnt = 0;
                for (int i = 0; i < m; i++) cnt += (s_fi[i] <= x) ? 1 : 0;
                int nx = z + cnt;
                if (nx == x) break;
                x = nx;
            }
            val = 0.f;
            fi = x;
        }
        int k = fi % Kk;
        int eloc = fi / Kk;
        int eg = b * EPGn + eloc;
        int o = b * Xx + r;
        out[o]          = val;
        out[6400 + o]   = (float)g_src[eg];
        out[12800 + o]  = (float)g_dst[eg];
        out[19200 + o]  = s_p[k];
        out[25600 + o]  = (float)s_cls[k];
    }
    if (threadIdx.x == 0) out[32000 + b] = 100.f;
}

// ---------------- launcher ----------------
extern "C" void kernel_launch(void* const* d_in, const int* in_sizes, int n_in,
                              void* d_out, int out_size) {
    const float* obj_lin  = (const float*)d_in[0];
    const float* obj_conv = (const float*)d_in[1];
    const float* rel_lin  = (const float*)d_in[2];
    const int*   ri       = (const int*)d_in[3];
    const float* W_obj    = (const float*)d_in[4];
    const float* W_conv   = (const float*)d_in[5];
    const float* W_rel    = (const float*)d_in[6];
    float* out = (float*)d_out;

    detect_k<<<1, 1>>>(ri);
    prep_k<<<(En + 255) / 256, 256>>>(ri);
    l1_k<<<Pn, 256>>>(W_obj, W_conv, W_rel);
    gemm_k<<<NBLK_NODE + NBLK_REL, 128>>>(obj_lin, obj_conv, rel_lin, W_obj, W_conv, W_rel);
    node_reduce_k<<<(NNODES * Pn / 4 + 255) / 256, 256>>>();
    edge_max_k<<<Bn * Pn, 256>>>();
    final_k<<<Bn, 32>>>(out);
}

// round 16
// speedup vs baseline: 1.9044x; 1.4474x over previous
#include <cuda_runtime.h>
#include <cuda_fp16.h>
#include <math.h>

// ---------------- problem constants ----------------
#define Pn      50
#define NNODES  3200
#define EPGn    2048
#define En      131072
#define Bn      64
#define NPGn    50
#define D_LIN   1024
#define D_CONV  12544
#define D_REL   256
#define Kk      10
#define Xx      100

// node GEMM split-K: total K = 1024 + 12544 = 13568 = 53 * 256
#define NSEG    53
#define KSEG    256
#define BM      128
#define NBLK_NODE (NSEG * (NNODES / BM))   // 53 * 25 = 1325
#define NBLK_REL  (En / BM)                // 1024

// smem tile geometry (in halfs). Pitch 40 halfs = 80B: 8 consecutive rows land on
// 8 distinct 16B groups mod 128B -> ldmatrix conflict-free.
#define PA      40
#define AHh     0                    // A hi: 128 rows
#define ALh     (128 * PA)           // 5120
#define BHh     (2 * 128 * PA)       // 10240: B hi, 64 n-rows (50 data + 14 zero)
#define BLh     (BHh + 64 * PA)      // 12800
#define SMH_TOT (BLh + 64 * PA)      // 15360 halfs = 30720 B

// ---------------- device scratch (static, no allocation) ----------------
__device__ float g_part[(size_t)NSEG * NNODES * Pn];   // split-K partials
__device__ float g_node[NNODES * Pn];                  // node features [3200,50]
__device__ float g_relT[(size_t)Pn * En];              // rel GEMM output, transposed [50, E]
__device__ float g_logits[Bn * Pn];
__device__ int   g_amax[Bn * Pn];
__device__ unsigned char g_srcl[En];
__device__ unsigned char g_dstl[En];
__device__ int   g_src[En];
__device__ int   g_dst[En];
__device__ float g_L1W[Pn];
__device__ float g_L1R[Pn];
__device__ int   g_is64;

// ---------------- helpers ----------------
__device__ __forceinline__ unsigned smem_u32(const void* p) {
    unsigned a;
    asm("{ .reg .u64 t; cvta.to.shared.u64 t, %1; cvt.u32.u64 %0, t; }" : "=r"(a) : "l"(p));
    return a;
}
__device__ __forceinline__ unsigned h2u(__half2 h) {
    union { __half2 h; unsigned u; } c; c.h = h; return c.u;
}
#define LDSM4(r0, r1, r2, r3, addr) \
    asm volatile("ldmatrix.sync.aligned.m8n8.x4.shared.b16 {%0,%1,%2,%3}, [%4];" \
                 : "=r"(r0), "=r"(r1), "=r"(r2), "=r"(r3) : "r"(addr))
__device__ __forceinline__ void mma16816(float d[4], unsigned a0, unsigned a1,
                                         unsigned a2, unsigned a3,
                                         unsigned b0, unsigned b1) {
    asm volatile(
        "mma.sync.aligned.m16n8k16.row.col.f32.f16.f16.f32 "
        "{%0,%1,%2,%3}, {%4,%5,%6,%7}, {%8,%9}, {%0,%1,%2,%3};"
        : "+f"(d[0]), "+f"(d[1]), "+f"(d[2]), "+f"(d[3])
        : "r"(a0), "r"(a1), "r"(a2), "r"(a3), "r"(b0), "r"(b1));
}

// ---------------- dtype detection for relation_indexes ----------------
__global__ void detect_k(const int* __restrict__ ri) {
    int nz = 0;
    for (int i = 0; i < 64; i++) nz |= ri[2 * i + 1];
    g_is64 = (nz == 0) ? 1 : 0;
}

__global__ void prep_k(const int* __restrict__ ri) {
    int e = blockIdx.x * blockDim.x + threadIdx.x;
    if (e >= En) return;
    int s, d;
    if (g_is64) {
        s = (int)((const long long*)ri)[e];
        d = (int)((const long long*)ri)[En + e];
    } else {
        s = ri[e];
        d = ri[En + e];
    }
    g_src[e] = s;
    g_dst[e] = d;
    int b = e >> 11;
    g_srcl[e] = (unsigned char)(s - b * NPGn);
    g_dstl[e] = (unsigned char)(d - b * NPGn);
}

// ---------------- column L1 norms of the weight matrices ----------------
__global__ void l1_k(const float* __restrict__ Wo, const float* __restrict__ Wc,
                     const float* __restrict__ Wr) {
    int c = blockIdx.x;
    int t = threadIdx.x;  // 256 threads
    float sw = 0.f, sr = 0.f;
    for (int dd = t; dd < D_LIN; dd += 256)  sw += fabsf(Wo[dd * Pn + c]);
    for (int dd = t; dd < D_CONV; dd += 256) sw += fabsf(Wc[dd * Pn + c]);
    if (t < D_REL) sr = fabsf(Wr[t * Pn + c]);
    __shared__ float shw[256];
    __shared__ float shr[256];
    shw[t] = sw; shr[t] = sr;
    __syncthreads();
    for (int o = 128; o > 0; o >>= 1) {
        if (t < o) { shw[t] += shw[t + o]; shr[t] += shr[t + o]; }
        __syncthreads();
    }
    if (t == 0) { g_L1W[c] = shw[0]; g_L1R[c] = shr[0]; }
}

// ================= HMMA GEMM (fp16 2x2 split, fp32-equivalent) =================
// Block: 256 threads = 8 warps, tile M128 x N56(pad 64) x K256 (8 chunks of 32).
// a = ah + al (x2^8), w = wh + wl (x2^16); acc = 2^24 * (ah wh + ah wl + al wh);
// epilogue x 2^-24 (exact). Dropped al*wl ~ 2^-22 relative -> decisions unaffected.
// Warp w owns rows [w*16, w*16+16); loops 7 n-tiles of 8; mma.sync m16n8k16.
__global__ void __launch_bounds__(256, 3) gemm_hmma(
    const float* __restrict__ obj_lin, const float* __restrict__ obj_conv,
    const float* __restrict__ rel_lin,
    const float* __restrict__ Wo, const float* __restrict__ Wc,
    const float* __restrict__ Wr) {

    __shared__ __align__(16) __half smh[SMH_TOT];

    int t = threadIdx.x;
    int wid = t >> 5, l = t & 31;
    int blk = blockIdx.x;

    const float* A;
    const float* W;
    int lda, row0, s = 0;
    bool isrel = (blk >= NBLK_NODE);
    if (isrel) {
        row0 = (blk - NBLK_NODE) * BM;
        A = rel_lin; lda = D_REL; W = Wr;
    } else {
        int rb = blk % 25;
        s = blk / 25;
        row0 = rb * BM;
        if (s < 4) { A = obj_lin + (size_t)s * KSEG; lda = D_LIN; W = Wo + (size_t)s * KSEG * Pn; }
        else       { A = obj_conv + (size_t)(s * KSEG - D_LIN); lda = D_CONV; W = Wc + (size_t)(s * KSEG - D_LIN) * Pn; }
    }

    unsigned sb = smem_u32(smh);
    int q = l >> 3, lr = l & 7;

    // ldmatrix lane->address maps (bytes).
    // A x4: m0 rows0-7/k0-7, m1 rows8-15/k0-7, m2 rows0-7/k8-15, m3 rows8-15/k8-15
    unsigned a_hi = sb + (unsigned)(((wid * 16 + (q & 1) * 8 + lr) * PA + (q >> 1) * 8) * 2);
    // B x4 (n-tile pair): m0 nt/k0-7, m1 nt/k8-15, m2 nt+1/k0-7, m3 nt+1/k8-15
    unsigned b_hi = sb + (unsigned)(BHh * 2 + (((q >> 1) * 8 + lr) * PA + (q & 1) * 8) * 2);

    // zero B pad rows (n = 50..63) once; data rows rewritten each chunk
    for (int j = t; j < 14 * 32; j += 256) {
        int n = 50 + (j >> 5), kk = j & 31;
        smh[BHh + n * PA + kk] = __float2half(0.f);
        smh[BLh + n * PA + kk] = __float2half(0.f);
    }

    float acc[7][4];
#pragma unroll
    for (int n = 0; n < 7; n++)
#pragma unroll
        for (int i = 0; i < 4; i++) acc[n][i] = 0.f;

    for (int ch = 0; ch < 8; ch++) {
        int kb = ch * 32;
        // ---- A: 128 rows x 32 k fp32 -> x256 -> f16 hi/lo split
#pragma unroll
        for (int j = 0; j < 4; j++) {
            int idx = t + 256 * j;
            int rr = idx >> 3, q4 = idx & 7;
            float4 v = *(const float4*)&A[(size_t)(row0 + rr) * lda + kb + q4 * 4];
            v.x *= 256.f; v.y *= 256.f; v.z *= 256.f; v.w *= 256.f;
            __half2 h01 = __floats2half2_rn(v.x, v.y);
            __half2 h23 = __floats2half2_rn(v.z, v.w);
            float2 f01 = __half22float2(h01), f23 = __half22float2(h23);
            __half2 l01 = __floats2half2_rn(v.x - f01.x, v.y - f01.y);
            __half2 l23 = __floats2half2_rn(v.z - f23.x, v.w - f23.y);
            int hoff = rr * PA + q4 * 4;
            *(uint2*)&smh[AHh + hoff] = make_uint2(h2u(h01), h2u(h23));
            *(uint2*)&smh[ALh + hoff] = make_uint2(h2u(l01), h2u(l23));
        }
        // ---- B: W chunk [32 k x 50 n] fp32 -> transposed [n][k], x65536, split
        {
            const float* Wt = W + (size_t)kb * Pn;
#pragma unroll 2
            for (int j = t; j < 32 * Pn; j += 256) {
                int kk = j / Pn, n = j - kk * Pn;
                float w = Wt[j] * 65536.f;
                __half wh = __float2half_rn(w);
                __half wl = __float2half_rn(w - __half2float(wh));
                smh[BHh + n * PA + kk] = wh;
                smh[BLh + n * PA + kk] = wl;
            }
        }
        __syncthreads();

#pragma unroll
        for (int ks = 0; ks < 2; ks++) {
            unsigned ah0, ah1, ah2, ah3, al0, al1, al2, al3;
            LDSM4(ah0, ah1, ah2, ah3, a_hi + ks * 32);
            LDSM4(al0, al1, al2, al3, a_hi + ks * 32 + ALh * 2);
#pragma unroll
            for (int ntp = 0; ntp < 4; ntp++) {
                unsigned bo = b_hi + (unsigned)(ntp * 16 * PA * 2) + ks * 32;
                unsigned h0, h1, h2, h3, l0, l1, l2, l3;
                LDSM4(h0, h1, h2, h3, bo);
                LDSM4(l0, l1, l2, l3, bo + (BLh - BHh) * 2);
                int nt = 2 * ntp;
                mma16816(acc[nt], ah0, ah1, ah2, ah3, h0, h1);
                mma16816(acc[nt], ah0, ah1, ah2, ah3, l0, l1);
                mma16816(acc[nt], al0, al1, al2, al3, h0, h1);
                if (ntp < 3) {
                    mma16816(acc[nt + 1], ah0, ah1, ah2, ah3, h2, h3);
                    mma16816(acc[nt + 1], ah0, ah1, ah2, ah3, l2, l3);
                    mma16816(acc[nt + 1], al0, al1, al2, al3, h2, h3);
                }
            }
        }
        __syncthreads();
    }

    // ---- epilogue: x 2^-24 (exact), write out
    const float sc = 5.9604644775390625e-8f;  // 2^-24
    int g = l >> 2, tig = l & 3;
    int r_lo = row0 + wid * 16 + g;
    if (!isrel) {
        float* o0 = g_part + ((size_t)s * NNODES + r_lo) * Pn;
        float* o1 = o0 + 8 * Pn;
#pragma unroll
        for (int nt = 0; nt < 7; nt++) {
            int c = nt * 8 + 2 * tig;
            if (c < Pn) {
                *(float2*)&o0[c] = make_float2(acc[nt][0] * sc, acc[nt][1] * sc);
                *(float2*)&o1[c] = make_float2(acc[nt][2] * sc, acc[nt][3] * sc);
            }
        }
    } else {
#pragma unroll
        for (int nt = 0; nt < 7; nt++) {
            int c = nt * 8 + 2 * tig;
            if (c < Pn) {
                g_relT[(size_t)c * En + r_lo]           = acc[nt][0] * sc;
                g_relT[(size_t)(c + 1) * En + r_lo]     = acc[nt][1] * sc;
                g_relT[(size_t)c * En + r_lo + 8]       = acc[nt][2] * sc;
                g_relT[(size_t)(c + 1) * En + r_lo + 8] = acc[nt][3] * sc;
            }
        }
    }
}

// ---------------- split-K reduction (float4 streaming) ----------------
__global__ void node_reduce_k() {
    int i4 = blockIdx.x * 256 + threadIdx.x;
    if (i4 >= NNODES * Pn / 4) return;
    float4 s = make_float4(0.f, 0.f, 0.f, 0.f);
    const float4* p = reinterpret_cast<const float4*>(g_part) + i4;
#pragma unroll 4
    for (int seg = 0; seg < NSEG; seg++) {
        float4 v = p[(size_t)seg * (NNODES * Pn / 4)];
        s.x += v.x; s.y += v.y; s.z += v.z; s.w += v.w;
    }
    reinterpret_cast<float4*>(g_node)[i4] = s;
}

// ---------------- per (graph, class) max over 2048 edges, with argmax ----------------
__global__ void edge_max_k() {
    int bc = blockIdx.x;
    int b = bc / Pn, c = bc % Pn;
    __shared__ float nodesm[NPGn];
    int t = threadIdx.x;  // 256
    if (t < NPGn) nodesm[t] = g_node[(b * NPGn + t) * Pn + c];
    __syncthreads();
    const float* rptr = g_relT + (size_t)c * En + (size_t)b * EPGn;
    const unsigned char* sp = g_srcl + (size_t)b * EPGn;
    const unsigned char* dp = g_dstl + (size_t)b * EPGn;
    float best = -3.402823466e38f;
    int bi = 0;
    for (int e = t; e < EPGn; e += 256) {
        float v = rptr[e] + nodesm[sp[e]] + nodesm[dp[e]];
        if (v > best) { best = v; bi = e; }  // strict > keeps lowest index on ties
    }
    __shared__ float sv[256];
    __shared__ int si[256];
    sv[t] = best; si[t] = bi;
    __syncthreads();
    for (int o = 128; o > 0; o >>= 1) {
        if (t < o) {
            float v2 = sv[t + o];
            int i2 = si[t + o];
            if (v2 > sv[t] || (v2 == sv[t] && i2 < si[t])) { sv[t] = v2; si[t] = i2; }
        }
        __syncthreads();
    }
    if (t == 0) { g_logits[bc] = sv[0]; g_amax[bc] = si[0]; }
}

// ---------------- final: top-K classes, analytic relevances, top-X, outputs ----------------
__global__ void final_k(float* __restrict__ out) {
    int b = blockIdx.x;
    __shared__ float s_p[Kk];
    __shared__ int s_cls[Kk];
    __shared__ float s_val[Kk];
    __shared__ int s_fi[Kk];
    __shared__ int s_m;

    if (threadIdx.x == 0) {
        float pr[Pn];
        bool used[Pn];
        for (int c = 0; c < Pn; c++) {
            float x = g_logits[b * Pn + c];
            pr[c] = 1.f / (1.f + expf(-x));
            used[c] = false;
        }
        for (int k = 0; k < Kk; k++) {
            int bcx = 0;
            float bv = -1.f;
            for (int c = 0; c < Pn; c++)
                if (!used[c] && pr[c] > bv) { bv = pr[c]; bcx = c; }
            used[bcx] = true;
            s_cls[k] = bcx;
            s_p[k] = bv;
        }
        float tv[Kk];
        int tf[Kk];
        for (int k = 0; k < Kk; k++) {
            int c = s_cls[k];
            float x = g_logits[b * Pn + c];
            float p = s_p[k];
            float q = 1.f / (1.f + expf(x));
            float sg = p * q;
            int eloc = g_amax[b * Pn + c];
            int eg = b * EPGn + eloc;
            float mult = (g_srcl[eg] == g_dstl[eg]) ? 2.f : 1.f;
            float rn = mult * sg * g_L1W[c];
            float re = sg * g_L1R[c];
            tv[k] = rn * re * rn * p;
            tf[k] = eloc * Kk + k;
        }
        for (int i = 1; i < Kk; i++) {
            float v = tv[i];
            int f = tf[i];
            int j = i - 1;
            while (j >= 0 && (tv[j] < v || (tv[j] == v && tf[j] > f))) {
                tv[j + 1] = tv[j]; tf[j + 1] = tf[j]; j--;
            }
            tv[j + 1] = v; tf[j + 1] = f;
        }
        int m = 0;
        while (m < Kk && tv[m] > 0.f) m++;
        for (int k = 0; k < Kk; k++) { s_val[k] = tv[k]; s_fi[k] = tf[k]; }
        s_m = m;
    }
    __syncthreads();

    int m = s_m;
    for (int r = threadIdx.x; r < Xx; r += blockDim.x) {
        float val;
        int fi;
        if (r < m) {
            val = s_val[r];
            fi = s_fi[r];
        } else {
            int z = r - m;
            int x = z;
            for (int it = 0; it < Kk + 2; it++) {
                int cnt = 0;
                for (int i = 0; i < m; i++) cnt += (s_fi[i] <= x) ? 1 : 0;
                int nx = z + cnt;
                if (nx == x) break;
                x = nx;
            }
            val = 0.f;
            fi = x;
        }
        int k = fi % Kk;
        int eloc = fi / Kk;
        int eg = b * EPGn + eloc;
        int o = b * Xx + r;
        out[o]          = val;
        out[6400 + o]   = (float)g_src[eg];
        out[12800 + o]  = (float)g_dst[eg];
        out[19200 + o]  = s_p[k];
        out[25600 + o]  = (float)s_cls[k];
    }
    if (threadIdx.x == 0) out[32000 + b] = 100.f;
}

// ---------------- launcher ----------------
extern "C" void kernel_launch(void* const* d_in, const int* in_sizes, int n_in,
                              void* d_out, int out_size) {
    const float* obj_lin  = (const float*)d_in[0];
    const float* obj_conv = (const float*)d_in[1];
    const float* rel_lin  = (const float*)d_in[2];
    const int*   ri       = (const int*)d_in[3];
    const float* W_obj    = (const float*)d_in[4];
    const float* W_conv   = (const float*)d_in[5];
    const float* W_rel    = (const float*)d_in[6];
    float* out = (float*)d_out;

    detect_k<<<1, 1>>>(ri);
    prep_k<<<(En + 255) / 256, 256>>>(ri);
    l1_k<<<Pn, 256>>>(W_obj, W_conv, W_rel);
    gemm_hmma<<<NBLK_NODE + NBLK_REL, 256>>>(obj_lin, obj_conv, rel_lin, W_obj, W_conv, W_rel);
    node_reduce_k<<<(NNODES * Pn / 4 + 255) / 256, 256>>>();
    edge_max_k<<<Bn * Pn, 256>>>();
    final_k<<<Bn, 32>>>(out);
}

// round 17
// speedup vs baseline: 2.0789x; 1.0916x over previous
#include <cuda_runtime.h>
#include <cuda_fp16.h>
#include <math.h>

// ---------------- problem constants ----------------
#define Pn      50
#define NNODES  3200
#define EPGn    2048
#define En      131072
#define Bn      64
#define NPGn    50
#define D_LIN   1024
#define D_CONV  12544
#define D_REL   256
#define Kk      10
#define Xx      100

// node GEMM split-K: total K = 1024 + 12544 = 13568 = 53 * 256
#define NSEG    53
#define KSEG    256
#define BM      128
#define NBLK_NODE (NSEG * (NNODES / BM))   // 53 * 25 = 1325
#define NBLK_REL  (En / BM)                // 1024
#define NCH_NODE  (13568 / 32)             // 424 k-chunks of 32
#define NCH_TOT   (NCH_NODE + D_REL / 32)  // + 8 rel chunks = 432

// smem tile geometry (in halfs). Pitch 40 halfs = 80B: 8 consecutive rows land on
// 8 distinct 16B groups mod 128B -> ldmatrix conflict-free.
#define PA      40
#define AHh     0                    // A hi: 128 rows
#define ALh     (128 * PA)           // 5120
#define Bh      (2 * 128 * PA)       // 10240: B chunk tile (hi 64xPA, then lo 64xPA)
#define BLOFF   (64 * PA)            // 2560 halfs: lo offset within B tile
#define CHUNK_H (2 * 64 * PA)        // 5120 halfs = one preconverted W chunk tile
#define SMH_TOT (Bh + CHUNK_H)       // 15360 halfs = 30720 B

// ---------------- device scratch (static, no allocation) ----------------
__device__ float g_part[(size_t)NSEG * NNODES * Pn];   // split-K partials
__device__ float g_node[NNODES * Pn];                  // node features [3200,50]
__device__ float g_relT[(size_t)Pn * En];              // rel GEMM output, transposed [50, E]
__device__ __half g_wsplit[(size_t)NCH_TOT * CHUNK_H]; // preconverted W tiles (hi/lo)
__device__ float g_logits[Bn * Pn];
__device__ int   g_amax[Bn * Pn];
__device__ unsigned char g_srcl[En];
__device__ unsigned char g_dstl[En];
__device__ int   g_src[En];
__device__ int   g_dst[En];
__device__ float g_L1W[Pn];
__device__ float g_L1R[Pn];
__device__ int   g_is64;

// ---------------- helpers ----------------
__device__ __forceinline__ unsigned smem_u32(const void* p) {
    unsigned a;
    asm("{ .reg .u64 t; cvta.to.shared.u64 t, %1; cvt.u32.u64 %0, t; }" : "=r"(a) : "l"(p));
    return a;
}
__device__ __forceinline__ unsigned h2u(__half2 h) {
    union { __half2 h; unsigned u; } c; c.h = h; return c.u;
}
#define LDSM4(r0, r1, r2, r3, addr) \
    asm volatile("ldmatrix.sync.aligned.m8n8.x4.shared.b16 {%0,%1,%2,%3}, [%4];" \
                 : "=r"(r0), "=r"(r1), "=r"(r2), "=r"(r3) : "r"(addr))
__device__ __forceinline__ void mma16816(float d[4], unsigned a0, unsigned a1,
                                         unsigned a2, unsigned a3,
                                         unsigned b0, unsigned b1) {
    asm volatile(
        "mma.sync.aligned.m16n8k16.row.col.f32.f16.f16.f32 "
        "{%0,%1,%2,%3}, {%4,%5,%6,%7}, {%8,%9}, {%0,%1,%2,%3};"
        : "+f"(d[0]), "+f"(d[1]), "+f"(d[2]), "+f"(d[3])
        : "r"(a0), "r"(a1), "r"(a2), "r"(a3), "r"(b0), "r"(b1));
}

// ---------------- dtype detection for relation_indexes ----------------
__global__ void detect_k(const int* __restrict__ ri) {
    int nz = 0;
    for (int i = 0; i < 64; i++) nz |= ri[2 * i + 1];
    g_is64 = (nz == 0) ? 1 : 0;
}

__global__ void prep_k(const int* __restrict__ ri) {
    int e = blockIdx.x * blockDim.x + threadIdx.x;
    if (e >= En) return;
    int s, d;
    if (g_is64) {
        s = (int)((const long long*)ri)[e];
        d = (int)((const long long*)ri)[En + e];
    } else {
        s = ri[e];
        d = ri[En + e];
    }
    g_src[e] = s;
    g_dst[e] = d;
    int b = e >> 11;
    g_srcl[e] = (unsigned char)(s - b * NPGn);
    g_dstl[e] = (unsigned char)(d - b * NPGn);
}

// ---------------- column L1 norms of the weight matrices ----------------
__global__ void l1_k(const float* __restrict__ Wo, const float* __restrict__ Wc,
                     const float* __restrict__ Wr) {
    int c = blockIdx.x;
    int t = threadIdx.x;  // 256 threads
    float sw = 0.f, sr = 0.f;
    for (int dd = t; dd < D_LIN; dd += 256)  sw += fabsf(Wo[dd * Pn + c]);
    for (int dd = t; dd < D_CONV; dd += 256) sw += fabsf(Wc[dd * Pn + c]);
    if (t < D_REL) sr = fabsf(Wr[t * Pn + c]);
    __shared__ float shw[256];
    __shared__ float shr[256];
    shw[t] = sw; shr[t] = sr;
    __syncthreads();
    for (int o = 128; o > 0; o >>= 1) {
        if (t < o) { shw[t] += shw[t + o]; shr[t] += shr[t + o]; }
        __syncthreads();
    }
    if (t == 0) { g_L1W[c] = shw[0]; g_L1R[c] = shr[0]; }
}

// ---------------- W split precompute ----------------
// Chunk cc covers k [cc*32, cc*32+32): cc<424 from node W (Wo k<1024, else Wc),
// cc>=424 from Wr. Output tile (n-major, pitch PA, rows 50..63 zero):
//   g_wsplit[cc*CHUNK_H + n*PA + kk]        = wh(W[k][n] * 2^16)
//   g_wsplit[cc*CHUNK_H + BLOFF + n*PA+kk]  = wl
__global__ void wsplit_k(const float* __restrict__ Wo, const float* __restrict__ Wc,
                         const float* __restrict__ Wr) {
    int cc = blockIdx.x;
    int t = threadIdx.x;  // 128
    int kbase = cc * 32;
    const float* W;
    if (cc >= NCH_NODE)      { W = Wr + (size_t)(kbase - 13568) * Pn; }
    else if (kbase < D_LIN)  { W = Wo + (size_t)kbase * Pn; }
    else                     { W = Wc + (size_t)(kbase - D_LIN) * Pn; }
    __half* out = g_wsplit + (size_t)cc * CHUNK_H;
    for (int j = t; j < 64 * 32; j += 128) {
        int n = j >> 5, kk = j & 31;
        __half wh, wl;
        if (n < Pn) {
            float w = W[(size_t)kk * Pn + n] * 65536.f;
            wh = __float2half_rn(w);
            wl = __float2half_rn(w - __half2float(wh));
        } else {
            wh = __float2half(0.f);
            wl = wh;
        }
        out[n * PA + kk] = wh;
        out[BLOFF + n * PA + kk] = wl;
    }
}

// ================= HMMA GEMM (fp16 2x2 split, fp32-equivalent) =================
// Block: 256 threads = 8 warps, tile M128 x N56(pad 64) x K256 (8 chunks of 32).
// a = ah + al (x2^8), w = wh + wl (x2^16); acc = 2^24 * (ah wh + ah wl + al wh);
// epilogue x 2^-24 (exact). W tiles preconverted by wsplit_k -> plain float4 copy.
__global__ void __launch_bounds__(256, 3) gemm_hmma(
    const float* __restrict__ obj_lin, const float* __restrict__ obj_conv,
    const float* __restrict__ rel_lin) {

    __shared__ __align__(16) __half smh[SMH_TOT];

    int t = threadIdx.x;
    int wid = t >> 5, l = t & 31;
    int blk = blockIdx.x;

    const float* A;
    int lda, row0, s = 0, cc0;
    bool isrel = (blk >= NBLK_NODE);
    if (isrel) {
        row0 = (blk - NBLK_NODE) * BM;
        A = rel_lin; lda = D_REL; cc0 = NCH_NODE;
    } else {
        int rb = blk % 25;
        s = blk / 25;
        row0 = rb * BM;
        cc0 = s * 8;
        if (s < 4) { A = obj_lin + (size_t)s * KSEG; lda = D_LIN; }
        else       { A = obj_conv + (size_t)(s * KSEG - D_LIN); lda = D_CONV; }
    }

    unsigned sb = smem_u32(smh);
    int q = l >> 3, lr = l & 7;

    // ldmatrix lane->address maps (bytes).
    unsigned a_hi = sb + (unsigned)(((wid * 16 + (q & 1) * 8 + lr) * PA + (q >> 1) * 8) * 2);
    unsigned b_hi = sb + (unsigned)(Bh * 2 + (((q >> 1) * 8 + lr) * PA + (q & 1) * 8) * 2);

    float acc[7][4];
#pragma unroll
    for (int n = 0; n < 7; n++)
#pragma unroll
        for (int i = 0; i < 4; i++) acc[n][i] = 0.f;

    for (int ch = 0; ch < 8; ch++) {
        int kb = ch * 32;
        // ---- A: 128 rows x 32 k fp32 -> x256 -> f16 hi/lo split
#pragma unroll
        for (int j = 0; j < 4; j++) {
            int idx = t + 256 * j;
            int rr = idx >> 3, q4 = idx & 7;
            float4 v = *(const float4*)&A[(size_t)(row0 + rr) * lda + kb + q4 * 4];
            v.x *= 256.f; v.y *= 256.f; v.z *= 256.f; v.w *= 256.f;
            __half2 h01 = __floats2half2_rn(v.x, v.y);
            __half2 h23 = __floats2half2_rn(v.z, v.w);
            float2 f01 = __half22float2(h01), f23 = __half22float2(h23);
            __half2 l01 = __floats2half2_rn(v.x - f01.x, v.y - f01.y);
            __half2 l23 = __floats2half2_rn(v.z - f23.x, v.w - f23.y);
            int hoff = rr * PA + q4 * 4;
            *(uint2*)&smh[AHh + hoff] = make_uint2(h2u(h01), h2u(h23));
            *(uint2*)&smh[ALh + hoff] = make_uint2(h2u(l01), h2u(l23));
        }
        // ---- B: preconverted chunk tile, straight float4 copy (10240 B)
        {
            const float4* src = (const float4*)(g_wsplit + (size_t)(cc0 + ch) * CHUNK_H);
            float4* dst = (float4*)&smh[Bh];
#pragma unroll
            for (int j = t; j < CHUNK_H / 8; j += 256) dst[j] = src[j];
        }
        __syncthreads();

#pragma unroll
        for (int ks = 0; ks < 2; ks++) {
            unsigned ah0, ah1, ah2, ah3, al0, al1, al2, al3;
            LDSM4(ah0, ah1, ah2, ah3, a_hi + ks * 32);
            LDSM4(al0, al1, al2, al3, a_hi + ks * 32 + ALh * 2);
#pragma unroll
            for (int ntp = 0; ntp < 4; ntp++) {
                unsigned bo = b_hi + (unsigned)(ntp * 16 * PA * 2) + ks * 32;
                unsigned h0, h1, h2, h3, l0, l1, l2, l3;
                LDSM4(h0, h1, h2, h3, bo);
                LDSM4(l0, l1, l2, l3, bo + BLOFF * 2);
                int nt = 2 * ntp;
                mma16816(acc[nt], ah0, ah1, ah2, ah3, h0, h1);
                mma16816(acc[nt], ah0, ah1, ah2, ah3, l0, l1);
                mma16816(acc[nt], al0, al1, al2, al3, h0, h1);
                if (ntp < 3) {
                    mma16816(acc[nt + 1], ah0, ah1, ah2, ah3, h2, h3);
                    mma16816(acc[nt + 1], ah0, ah1, ah2, ah3, l2, l3);
                    mma16816(acc[nt + 1], al0, al1, al2, al3, h2, h3);
                }
            }
        }
        __syncthreads();
    }

    // ---- epilogue: x 2^-24 (exact), write out
    const float sc = 5.9604644775390625e-8f;  // 2^-24
    int g = l >> 2, tig = l & 3;
    int r_lo = row0 + wid * 16 + g;
    if (!isrel) {
        float* o0 = g_part + ((size_t)s * NNODES + r_lo) * Pn;
        float* o1 = o0 + 8 * Pn;
#pragma unroll
        for (int nt = 0; nt < 7; nt++) {
            int c = nt * 8 + 2 * tig;
            if (c < Pn) {
                *(float2*)&o0[c] = make_float2(acc[nt][0] * sc, acc[nt][1] * sc);
                *(float2*)&o1[c] = make_float2(acc[nt][2] * sc, acc[nt][3] * sc);
            }
        }
    } else {
#pragma unroll
        for (int nt = 0; nt < 7; nt++) {
            int c = nt * 8 + 2 * tig;
            if (c < Pn) {
                g_relT[(size_t)c * En + r_lo]           = acc[nt][0] * sc;
                g_relT[(size_t)(c + 1) * En + r_lo]     = acc[nt][1] * sc;
                g_relT[(size_t)c * En + r_lo + 8]       = acc[nt][2] * sc;
                g_relT[(size_t)(c + 1) * En + r_lo + 8] = acc[nt][3] * sc;
            }
        }
    }
}

// ---------------- split-K reduction (float4 streaming) ----------------
__global__ void node_reduce_k() {
    int i4 = blockIdx.x * 256 + threadIdx.x;
    if (i4 >= NNODES * Pn / 4) return;
    float4 s = make_float4(0.f, 0.f, 0.f, 0.f);
    const float4* p = reinterpret_cast<const float4*>(g_part) + i4;
#pragma unroll 4
    for (int seg = 0; seg < NSEG; seg++) {
        float4 v = p[(size_t)seg * (NNODES * Pn / 4)];
        s.x += v.x; s.y += v.y; s.z += v.z; s.w += v.w;
    }
    reinterpret_cast<float4*>(g_node)[i4] = s;
}

// ---------------- per (graph, class) max over 2048 edges, with argmax ----------------
__global__ void edge_max_k() {
    int bc = blockIdx.x;
    int b = bc / Pn, c = bc % Pn;
    __shared__ float nodesm[NPGn];
    int t = threadIdx.x;  // 256
    if (t < NPGn) nodesm[t] = g_node[(b * NPGn + t) * Pn + c];
    __syncthreads();
    const float* rptr = g_relT + (size_t)c * En + (size_t)b * EPGn;
    const unsigned char* sp = g_srcl + (size_t)b * EPGn;
    const unsigned char* dp = g_dstl + (size_t)b * EPGn;
    float best = -3.402823466e38f;
    int bi = 0;
    for (int e = t; e < EPGn; e += 256) {
        float v = rptr[e] + nodesm[sp[e]] + nodesm[dp[e]];
        if (v > best) { best = v; bi = e; }  // strict > keeps lowest index on ties
    }
    __shared__ float sv[256];
    __shared__ int si[256];
    sv[t] = best; si[t] = bi;
    __syncthreads();
    for (int o = 128; o > 0; o >>= 1) {
        if (t < o) {
            float v2 = sv[t + o];
            int i2 = si[t + o];
            if (v2 > sv[t] || (v2 == sv[t] && i2 < si[t])) { sv[t] = v2; si[t] = i2; }
        }
        __syncthreads();
    }
    if (t == 0) { g_logits[bc] = sv[0]; g_amax[bc] = si[0]; }
}

// ---------------- final: top-K classes, analytic relevances, top-X, outputs ----------------
__global__ void final_k(float* __restrict__ out) {
    int b = blockIdx.x;
    __shared__ float s_p[Kk];
    __shared__ int s_cls[Kk];
    __shared__ float s_val[Kk];
    __shared__ int s_fi[Kk];
    __shared__ int s_m;

    if (threadIdx.x == 0) {
        float pr[Pn];
        bool used[Pn];
        for (int c = 0; c < Pn; c++) {
            float x = g_logits[b * Pn + c];
            pr[c] = 1.f / (1.f + expf(-x));
            used[c] = false;
        }
        for (int k = 0; k < Kk; k++) {
            int bcx = 0;
            float bv = -1.f;
            for (int c = 0; c < Pn; c++)
                if (!used[c] && pr[c] > bv) { bv = pr[c]; bcx = c; }
            used[bcx] = true;
            s_cls[k] = bcx;
            s_p[k] = bv;
        }
        float tv[Kk];
        int tf[Kk];
        for (int k = 0; k < Kk; k++) {
            int c = s_cls[k];
            float x = g_logits[b * Pn + c];
            float p = s_p[k];
            float q = 1.f / (1.f + expf(x));
            float sg = p * q;
            int eloc = g_amax[b * Pn + c];
            int eg = b * EPGn + eloc;
            float mult = (g_srcl[eg] == g_dstl[eg]) ? 2.f : 1.f;
            float rn = mult * sg * g_L1W[c];
            float re = sg * g_L1R[c];
            tv[k] = rn * re * rn * p;
            tf[k] = eloc * Kk + k;
        }
        for (int i = 1; i < Kk; i++) {
            float v = tv[i];
            int f = tf[i];
            int j = i - 1;
            while (j >= 0 && (tv[j] < v || (tv[j] == v && tf[j] > f))) {
                tv[j + 1] = tv[j]; tf[j + 1] = tf[j]; j--;
            }
            tv[j + 1] = v; tf[j + 1] = f;
        }
        int m = 0;
        while (m < Kk && tv[m] > 0.f) m++;
        for (int k = 0; k < Kk; k++) { s_val[k] = tv[k]; s_fi[k] = tf[k]; }
        s_m = m;
    }
    __syncthreads();

    int m = s_m;
    for (int r = threadIdx.x; r < Xx; r += blockDim.x) {
        float val;
        int fi;
        if (r < m) {
            val = s_val[r];
            fi = s_fi[r];
        } else {
            int z = r - m;
            int x = z;
            for (int it = 0; it < Kk + 2; it++) {
                int cnt = 0;
                for (int i = 0; i < m; i++) cnt += (s_fi[i] <= x) ? 1 : 0;
                int nx = z + cnt;
                if (nx == x) break;
                x = nx;
            }
            val = 0.f;
            fi = x;
        }
        int k = fi % Kk;
        int eloc = fi / Kk;
        int eg = b * EPGn + eloc;
        int o = b * Xx + r;
        out[o]          = val;
        out[6400 + o]   = (float)g_src[eg];
        out[12800 + o]  = (float)g_dst[eg];
        out[19200 + o]  = s_p[k];
        out[25600 + o]  = (float)s_cls[k];
    }
    if (threadIdx.x == 0) out[32000 + b] = 100.f;
}

// ---------------- launcher ----------------
extern "C" void kernel_launch(void* const* d_in, const int* in_sizes, int n_in,
                              void* d_out, int out_size) {
    const float* obj_lin  = (const float*)d_in[0];
    const float* obj_conv = (const float*)d_in[1];
    const float* rel_lin  = (const float*)d_in[2];
    const int*   ri       = (const int*)d_in[3];
    const float* W_obj    = (const float*)d_in[4];
    const float* W_conv   = (const float*)d_in[5];
    const float* W_rel    = (const float*)d_in[6];
    float* out = (float*)d_out;

    detect_k<<<1, 1>>>(ri);
    prep_k<<<(En + 255) / 256, 256>>>(ri);
    wsplit_k<<<NCH_TOT, 128>>>(W_obj, W_conv, W_rel);
    l1_k<<<Pn, 256>>>(W_obj, W_conv, W_rel);
    gemm_hmma<<<NBLK_NODE + NBLK_REL, 256>>>(obj_lin, obj_conv, rel_lin);
    node_reduce_k<<<(NNODES * Pn / 4 + 255) / 256, 256>>>();
    edge_max_k<<<Bn * Pn, 256>>>();
    final_k<<<Bn, 32>>>(out);
}